// round 6
// baseline (speedup 1.0000x reference)
#include <cuda_runtime.h>
#include <cuda_bf16.h>
#include <cstdint>
#include <math.h>

#define HD 128
#define DD 8
#define TPB 512
#define SPB 128

typedef unsigned long long ull;
typedef unsigned int uint;

// B operands in per-lane mma-fragment order: [jt(16)][s(8)][lane(32)] x 4 bf16 (8B/lane)
__device__ __align__(16) __nv_bfloat16 g_bw2hi[16 * 8 * 32 * 4];
__device__ __align__(16) __nv_bfloat16 g_bw2lo[16 * 8 * 32 * 4];
__device__ __align__(16) __nv_bfloat16 g_bmhi[16 * 8 * 32 * 4];
__device__ __align__(16) __nv_bfloat16 g_bmlo[16 * 8 * 32 * 4];
__device__ float2 g_tab[1024];   // tanh table: {tanh(x_i), tanh(x_{i+1})-tanh(x_i)}

// ---------------- smem layout (bytes) ----------------
// A tiles fragment-packed: [blk(8)][s(8)][lane(32)][4 x uint] = 32768 B each
#define ATILE 32768
#define OFF_H1HI 0
#define OFF_H1LO (OFF_H1HI + ATILE)
#define OFF_S1HI (OFF_H1LO + ATILE)
#define OFF_S1LO (OFF_S1HI + ATILE)          // ends 131072
#define BSLICE   16384                       // 8 jt x 8 s x 32 lanes x 8B
#define OFF_BW2HI (OFF_S1LO + ATILE)
#define OFF_BW2LO (OFF_BW2HI + BSLICE)
#define OFF_BMHI  (OFF_BW2LO + BSLICE)
#define OFF_BMLO  (OFF_BMHI + BSLICE)        // ends 196608
#define OFF_TAB   (OFF_BMLO + BSLICE)        // 8192
#define OFF_W1    (OFF_TAB + 8192)           // 9*128*4 = 4608
#define OFF_W3    (OFF_W1 + 4608)            // 4096
#define OFF_B1    (OFF_W3 + 4096)            // 512
#define OFF_B2    (OFF_B1 + 512)             // 512
#define OFF_B3    (OFF_B2 + 512)             // 64
#define OFF_REDU  (OFF_B3 + 64)              // 128 samples x 10 floats = 5120
#define SMEM_BYTES (OFF_REDU + 5120)

// ---------------- helpers ----------------
__device__ __forceinline__ float tanh_lut(const float2* tab, float x) {
    float xc = fminf(fmaxf(x, -4.995f), 4.995f);
    float f  = fmaf(xc, 102.4f, 512.0f);
    int   i  = (int)f;
    float fr = f - (float)i;
    float2 e = tab[i];
    return fmaf(e.y, fr, e.x);
}
__device__ __forceinline__ ull pack2(float a, float b) {
    ull r; asm("mov.b64 %0, {%1,%2};" : "=l"(r) : "f"(a), "f"(b)); return r;
}
__device__ __forceinline__ float2 unpack2(ull v) {
    float2 f; asm("mov.b64 {%0,%1}, %2;" : "=f"(f.x), "=f"(f.y) : "l"(v)); return f;
}
__device__ __forceinline__ ull fma2(ull a, ull b, ull c) {
    ull r; asm("fma.rn.f32x2 %0, %1, %2, %3;" : "=l"(r) : "l"(a), "l"(b), "l"(c)); return r;
}
__device__ __forceinline__ ull add2(ull a, ull b) {
    ull r; asm("add.rn.f32x2 %0, %1, %2;" : "=l"(r) : "l"(a), "l"(b)); return r;
}
__device__ __forceinline__ void split_pack(float x0, float x1, uint& hi, uint& lo) {
    __nv_bfloat16 h0 = __float2bfloat16(x0);
    __nv_bfloat16 h1 = __float2bfloat16(x1);
    float r0 = x0 - __bfloat162float(h0);
    float r1 = x1 - __bfloat162float(h1);
    __nv_bfloat162 hp; hp.x = h0; hp.y = h1;
    __nv_bfloat162 lp; lp.x = __float2bfloat16(r0); lp.y = __float2bfloat16(r1);
    hi = *(uint*)&hp; lo = *(uint*)&lp;
}
__device__ __forceinline__ void mma_bf16(float* d, uint a0, uint a1, uint a2, uint a3,
                                         uint b0, uint b1) {
    asm("mma.sync.aligned.m16n8k16.row.col.f32.bf16.bf16.f32 "
        "{%0,%1,%2,%3},{%4,%5,%6,%7},{%8,%9},{%0,%1,%2,%3};"
        : "+f"(d[0]), "+f"(d[1]), "+f"(d[2]), "+f"(d[3])
        : "r"(a0), "r"(a1), "r"(a2), "r"(a3), "r"(b0), "r"(b1));
}

// ---------------- merged setup ----------------
__global__ void setup_kernel(const float* __restrict__ W1,
                             const float* __restrict__ W2,
                             const float* __restrict__ W3) {
    int idx = blockIdx.x * blockDim.x + threadIdx.x;   // 0..4095
    if (idx < 1024) {
        float x0 = (float)(idx - 512) * (1.0f / 102.4f);
        float x1 = (float)(idx - 511) * (1.0f / 102.4f);
        float t0 = tanhf(x0), t1 = tanhf(x1);
        g_tab[idx] = make_float2(t0, t1 - t0);
    }
    if (idx >= 16 * 8 * 32) return;
    int lane = idx & 31, s = (idx >> 5) & 7, jt = idx >> 8;
    int g = lane >> 2, c = lane & 3;
    int j = jt * 8 + g;
    int kb = s * 16 + c * 2;
    int ks[4] = {kb, kb + 1, kb + 8, kb + 9};
#pragma unroll
    for (int e = 0; e < 4; e++) {
        int k = ks[e];
        float w2 = W2[k * HD + j];
        float cc = 0.0f;
#pragma unroll
        for (int d = 0; d < DD; d++) cc += W1[d * HD + k] * W3[j * DD + d];
        float m = w2 * cc;
        __nv_bfloat16 whi = __float2bfloat16(w2);
        __nv_bfloat16 mhi = __float2bfloat16(m);
        int o = idx * 4 + e;
        g_bw2hi[o] = whi;
        g_bw2lo[o] = __float2bfloat16(w2 - __bfloat162float(whi));
        g_bmhi[o]  = mhi;
        g_bmlo[o]  = __float2bfloat16(m - __bfloat162float(mhi));
    }
}

// ---------------- main kernel ----------------
__global__ __launch_bounds__(TPB, 1)
void cnf_mma_kernel(const float* __restrict__ z,
                    const float* __restrict__ t,
                    const float* __restrict__ W1, const float* __restrict__ b1,
                    const float* __restrict__ b2, const float* __restrict__ b3,
                    const float* __restrict__ W3,
                    float* __restrict__ dz_out, float* __restrict__ dlogp_out,
                    int B)
{
    extern __shared__ __align__(16) char sm[];
    const int tid = threadIdx.x;
    const int wid = tid >> 5;
    const int lane = tid & 31;
    const int g = lane >> 2;
    const int c = lane & 3;
    const int blk = wid >> 1;       // 16-sample m-block (0..7)
    const int qh  = wid & 1;        // q-half within pair

    float*  W1s = (float*)(sm + OFF_W1);
    float*  W3s = (float*)(sm + OFF_W3);
    float*  b1s = (float*)(sm + OFF_B1);
    float*  b2s = (float*)(sm + OFF_B2);
    float*  b3s = (float*)(sm + OFF_B3);
    float*  redu = (float*)(sm + OFF_REDU);
    float2* tab = (float2*)(sm + OFF_TAB);

    // ---- stage misc + first B slice ----
    for (int i = tid; i < 1024; i += TPB) tab[i] = g_tab[i];
    for (int i = tid; i < 9 * HD; i += TPB) W1s[i] = W1[i];
    for (int i = tid; i < HD * DD; i += TPB) W3s[i] = W3[i];
    if (tid < HD) { b1s[tid] = b1[tid]; b2s[tid] = b2[tid]; }
    if (tid < DD) b3s[tid] = b3[tid];
    {
        uint4* d0 = (uint4*)(sm + OFF_BW2HI);
        uint4* d1 = (uint4*)(sm + OFF_BW2LO);
        uint4* d2 = (uint4*)(sm + OFF_BMHI);
        uint4* d3 = (uint4*)(sm + OFF_BMLO);
        const uint4* s0 = (const uint4*)g_bw2hi;
        const uint4* s1 = (const uint4*)g_bw2lo;
        const uint4* s2 = (const uint4*)g_bmhi;
        const uint4* s3 = (const uint4*)g_bmlo;
        for (int i = tid; i < 1024; i += TPB) {
            d0[i] = s0[i]; d1[i] = s1[i]; d2[i] = s2[i]; d3[i] = s3[i];
        }
    }
    __syncthreads();

    // ---- layer 1: thread = (sample row, k-quarter); writes fragment-packed tiles ----
    {
        const int s_loc = tid & 127;
        const int kq = tid >> 7;           // 0..3 -> 32 k's (16 pairs)
        const int sample0 = blockIdx.x * SPB + s_loc;
        float zr[DD];
        if (sample0 < B) {
            const float4* zv = (const float4*)(z + (size_t)sample0 * DD);
            float4 za = zv[0], zb = zv[1];
            zr[0]=za.x; zr[1]=za.y; zr[2]=za.z; zr[3]=za.w;
            zr[4]=zb.x; zr[5]=zb.y; zr[6]=zb.z; zr[7]=zb.w;
        } else {
#pragma unroll
            for (int d = 0; d < DD; d++) zr[d] = 0.0f;
        }
        const float tv = t[0];
        float h[32];
        const int kbase = kq * 32;
#pragma unroll
        for (int kk = 0; kk < 32; kk += 4) {
            float4 acc = *(const float4*)&b1s[kbase + kk];
#pragma unroll
            for (int d = 0; d < DD; d++) {
                float4 w = *(const float4*)&W1s[d * HD + kbase + kk];
                acc.x = fmaf(zr[d], w.x, acc.x);
                acc.y = fmaf(zr[d], w.y, acc.y);
                acc.z = fmaf(zr[d], w.z, acc.z);
                acc.w = fmaf(zr[d], w.w, acc.w);
            }
            float4 w8 = *(const float4*)&W1s[8 * HD + kbase + kk];
            h[kk + 0] = tanh_lut(tab, fmaf(tv, w8.x, acc.x));
            h[kk + 1] = tanh_lut(tab, fmaf(tv, w8.y, acc.y));
            h[kk + 2] = tanh_lut(tab, fmaf(tv, w8.z, acc.z));
            h[kk + 3] = tanh_lut(tab, fmaf(tv, w8.w, acc.w));
        }
        // fragment-packed scatter: row -> (blk_a, g_a, regrow); kp -> (s, c, reghalf)
        const int blk_a = s_loc >> 4;
        const int rowin = s_loc & 15;
        const int g_a = rowin & 7;
        const int regrow = rowin >> 3;
#pragma unroll
        for (int i = 0; i < 16; i++) {
            const int kp = kq * 16 + i;       // k pair index (k = 2*kp)
            const int s  = kp >> 3;
            const int w8 = kp & 7;
            const int cc = w8 & 3;
            const int reg = ((w8 >> 2) << 1) + regrow;   // a0..a3 slot
            const uint32_t off = (uint32_t)((((blk_a * 8 + s) * 32) + g_a * 4 + cc) * 16 + reg * 4);
            float x0 = h[2 * i], x1 = h[2 * i + 1];
            uint hi, lo;
            split_pack(x0, x1, hi, lo);
            *(uint*)(sm + OFF_H1HI + off) = hi;
            *(uint*)(sm + OFF_H1LO + off) = lo;
            float q0 = fmaf(-x0, x0, 1.0f);
            float q1 = fmaf(-x1, x1, 1.0f);
            split_pack(q0, q1, hi, lo);
            *(uint*)(sm + OFF_S1HI + off) = hi;
            *(uint*)(sm + OFF_S1LO + off) = lo;
        }
    }
    __syncthreads();

    // ---- GEMMs + epilogue, N in two halves; warp pair (blk, qh) splits q ----
    ull dzg[4] = {0,0,0,0}, dzh[4] = {0,0,0,0};
    float trg = 0.0f, trh = 0.0f;
    const uint32_t afoff = (uint32_t)((blk * 8) * 32 + lane) * 16;

#pragma unroll 1
    for (int nh = 0; nh < 2; nh++) {
        if (nh == 1) {
            __syncthreads();
            uint4* d0 = (uint4*)(sm + OFF_BW2HI);
            uint4* d1 = (uint4*)(sm + OFF_BW2LO);
            uint4* d2 = (uint4*)(sm + OFF_BMHI);
            uint4* d3 = (uint4*)(sm + OFF_BMLO);
            const uint4* s0 = (const uint4*)g_bw2hi + 1024;
            const uint4* s1 = (const uint4*)g_bw2lo + 1024;
            const uint4* s2 = (const uint4*)g_bmhi + 1024;
            const uint4* s3 = (const uint4*)g_bmlo + 1024;
            for (int i = tid; i < 1024; i += TPB) {
                d0[i] = s0[i]; d1[i] = s1[i]; d2[i] = s2[i]; d3[i] = s3[i];
            }
            __syncthreads();
        }

        float acc1[4][4], acc2[4][4];
#pragma unroll
        for (int q = 0; q < 4; q++)
#pragma unroll
            for (int e = 0; e < 4; e++) { acc1[q][e] = 0.0f; acc2[q][e] = 0.0f; }

#pragma unroll
        for (int s = 0; s < 8; s++) {
            const uint32_t ao = afoff + (uint32_t)s * 512;
            uint4 h1h = *(const uint4*)(sm + OFF_H1HI + ao);
            uint4 h1l = *(const uint4*)(sm + OFF_H1LO + ao);
            uint4 s1h = *(const uint4*)(sm + OFF_S1HI + ao);
            uint4 s1l = *(const uint4*)(sm + OFF_S1LO + ao);
#pragma unroll
            for (int q = 0; q < 4; q++) {
                const int bo = (((qh * 4 + q) * 8 + s) * 32 + lane) * 8;
                uint2 wh = *(const uint2*)(sm + OFF_BW2HI + bo);
                uint2 wl = *(const uint2*)(sm + OFF_BW2LO + bo);
                uint2 mh = *(const uint2*)(sm + OFF_BMHI + bo);
                uint2 ml = *(const uint2*)(sm + OFF_BMLO + bo);
                mma_bf16(acc1[q], h1h.x, h1h.y, h1h.z, h1h.w, wh.x, wh.y);
                mma_bf16(acc1[q], h1h.x, h1h.y, h1h.z, h1h.w, wl.x, wl.y);
                mma_bf16(acc1[q], h1l.x, h1l.y, h1l.z, h1l.w, wh.x, wh.y);
                mma_bf16(acc2[q], s1h.x, s1h.y, s1h.z, s1h.w, mh.x, mh.y);
                mma_bf16(acc2[q], s1h.x, s1h.y, s1h.z, s1h.w, ml.x, ml.y);
                mma_bf16(acc2[q], s1l.x, s1l.y, s1l.z, s1l.w, mh.x, mh.y);
            }
        }

        // epilogue for this half
#pragma unroll
        for (int q = 0; q < 4; q++) {
            const int j0 = (nh * 8 + qh * 4 + q) * 8 + 2 * c;
            const float b2x = b2s[j0], b2y = b2s[j0 + 1];
            const ull* w30 = (const ull*)(W3s + j0 * DD);
            const ull* w31 = (const ull*)(W3s + (j0 + 1) * DD);
            {
                float h2 = tanh_lut(tab, acc1[q][0] + b2x);
                trg = fmaf(acc2[q][0], fmaf(-h2, h2, 1.0f), trg);
                ull hp = pack2(h2, h2);
                dzg[0] = fma2(hp, w30[0], dzg[0]); dzg[1] = fma2(hp, w30[1], dzg[1]);
                dzg[2] = fma2(hp, w30[2], dzg[2]); dzg[3] = fma2(hp, w30[3], dzg[3]);
            }
            {
                float h2 = tanh_lut(tab, acc1[q][1] + b2y);
                trg = fmaf(acc2[q][1], fmaf(-h2, h2, 1.0f), trg);
                ull hp = pack2(h2, h2);
                dzg[0] = fma2(hp, w31[0], dzg[0]); dzg[1] = fma2(hp, w31[1], dzg[1]);
                dzg[2] = fma2(hp, w31[2], dzg[2]); dzg[3] = fma2(hp, w31[3], dzg[3]);
            }
            {
                float h2 = tanh_lut(tab, acc1[q][2] + b2x);
                trh = fmaf(acc2[q][2], fmaf(-h2, h2, 1.0f), trh);
                ull hp = pack2(h2, h2);
                dzh[0] = fma2(hp, w30[0], dzh[0]); dzh[1] = fma2(hp, w30[1], dzh[1]);
                dzh[2] = fma2(hp, w30[2], dzh[2]); dzh[3] = fma2(hp, w30[3], dzh[3]);
            }
            {
                float h2 = tanh_lut(tab, acc1[q][3] + b2y);
                trh = fmaf(acc2[q][3], fmaf(-h2, h2, 1.0f), trh);
                ull hp = pack2(h2, h2);
                dzh[0] = fma2(hp, w31[0], dzh[0]); dzh[1] = fma2(hp, w31[1], dzh[1]);
                dzh[2] = fma2(hp, w31[2], dzh[2]); dzh[3] = fma2(hp, w31[3], dzh[3]);
            }
        }
    }

    // ---- reduce over the 4 c-lanes ----
#pragma unroll
    for (int off = 1; off <= 2; off <<= 1) {
        trg += __shfl_xor_sync(0xffffffffu, trg, off);
        trh += __shfl_xor_sync(0xffffffffu, trh, off);
#pragma unroll
        for (int e = 0; e < 4; e++) {
            dzg[e] = add2(dzg[e], __shfl_xor_sync(0xffffffffu, dzg[e], off));
            dzh[e] = add2(dzh[e], __shfl_xor_sync(0xffffffffu, dzh[e], off));
        }
    }

    // ---- cross-pair combine: even warps stage partials, odd warps finish ----
    __syncthreads();   // protect redu region (also orders with B staging)
    if (qh == 0 && c == 0) {
        float* r0 = redu + (blk * 16 + g) * 10;
        float* r1 = redu + (blk * 16 + g + 8) * 10;
        float2 v;
        v = unpack2(dzg[0]); r0[0]=v.x; r0[1]=v.y;
        v = unpack2(dzg[1]); r0[2]=v.x; r0[3]=v.y;
        v = unpack2(dzg[2]); r0[4]=v.x; r0[5]=v.y;
        v = unpack2(dzg[3]); r0[6]=v.x; r0[7]=v.y;
        r0[8] = trg;
        v = unpack2(dzh[0]); r1[0]=v.x; r1[1]=v.y;
        v = unpack2(dzh[1]); r1[2]=v.x; r1[3]=v.y;
        v = unpack2(dzh[2]); r1[4]=v.x; r1[5]=v.y;
        v = unpack2(dzh[3]); r1[6]=v.x; r1[7]=v.y;
        r1[8] = trh;
    }
    __syncthreads();
    if (qh == 1 && c == 0) {
        float4 b3a = *(const float4*)&b3s[0];
        float4 b3b = *(const float4*)&b3s[4];
        const int sg = blockIdx.x * SPB + blk * 16 + g;
        const int sh = sg + 8;
        {
            const float* r0 = redu + (blk * 16 + g) * 10;
            float2 v0 = unpack2(dzg[0]), v1 = unpack2(dzg[1]);
            float2 v2 = unpack2(dzg[2]), v3 = unpack2(dzg[3]);
            if (sg < B) {
                float4* ov = (float4*)(dz_out + (size_t)sg * DD);
                ov[0] = make_float4(v0.x + r0[0] + b3a.x, v0.y + r0[1] + b3a.y,
                                    v1.x + r0[2] + b3a.z, v1.y + r0[3] + b3a.w);
                ov[1] = make_float4(v2.x + r0[4] + b3b.x, v2.y + r0[5] + b3b.y,
                                    v3.x + r0[6] + b3b.z, v3.y + r0[7] + b3b.w);
                dlogp_out[sg] = -(trg + r0[8]);
            }
        }
        {
            const float* r1 = redu + (blk * 16 + g + 8) * 10;
            float2 v0 = unpack2(dzh[0]), v1 = unpack2(dzh[1]);
            float2 v2 = unpack2(dzh[2]), v3 = unpack2(dzh[3]);
            if (sh < B) {
                float4* ov = (float4*)(dz_out + (size_t)sh * DD);
                ov[0] = make_float4(v0.x + r1[0] + b3a.x, v0.y + r1[1] + b3a.y,
                                    v1.x + r1[2] + b3a.z, v1.y + r1[3] + b3a.w);
                ov[1] = make_float4(v2.x + r1[4] + b3b.x, v2.y + r1[5] + b3b.y,
                                    v3.x + r1[6] + b3b.z, v3.y + r1[7] + b3b.w);
                dlogp_out[sh] = -(trh + r1[8]);
            }
        }
    }
}

extern "C" void kernel_launch(void* const* d_in, const int* in_sizes, int n_in,
                              void* d_out, int out_size) {
    const float* z  = (const float*)d_in[0];
    // d_in[1] = logp_z (unused: dlogp/dt = -trace only)
    const float* t  = (const float*)d_in[2];
    const float* W1 = (const float*)d_in[3];
    const float* b1 = (const float*)d_in[4];
    const float* W2 = (const float*)d_in[5];
    const float* b2 = (const float*)d_in[6];
    const float* W3 = (const float*)d_in[7];
    const float* b3 = (const float*)d_in[8];

    const int B = in_sizes[0] / DD;
    float* dz_out    = (float*)d_out;
    float* dlogp_out = dz_out + (size_t)B * DD;

    setup_kernel<<<16, 256>>>(W1, W2, W3);

    cudaFuncSetAttribute(cnf_mma_kernel,
                         cudaFuncAttributeMaxDynamicSharedMemorySize, SMEM_BYTES);
    cnf_mma_kernel<<<(B + SPB - 1) / SPB, TPB, SMEM_BYTES>>>(
        z, t, W1, b1, b2, b3, W3, dz_out, dlogp_out, B);
}

// round 7
// speedup vs baseline: 1.0944x; 1.0944x over previous
#include <cuda_runtime.h>
#include <cuda_bf16.h>
#include <cstdint>
#include <math.h>

#define HD 128
#define DD 8
#define TPB 256
#define SPB 128

typedef unsigned long long ull;
typedef unsigned int uint;

// B operands in per-lane mma-fragment order: [jt(16)][s(8)][lane(32)] x 4 bf16 (8B/lane)
__device__ __align__(16) __nv_bfloat16 g_bw2hi[16 * 8 * 32 * 4];
__device__ __align__(16) __nv_bfloat16 g_bw2lo[16 * 8 * 32 * 4];
__device__ __align__(16) __nv_bfloat16 g_bmhi[16 * 8 * 32 * 4];
__device__ __align__(16) __nv_bfloat16 g_bmlo[16 * 8 * 32 * 4];

// ---------------- smem layout (bytes) ----------------
// A tiles fragment-packed with location-permutation:
// [blk(8)][s(8)][loc(32)][16B]  where loc(f) = ((f&3)<<3)|(f>>2)
#define ATILE 32768
#define OFF_H1HI 0
#define OFF_H1LO (OFF_H1HI + ATILE)
#define OFF_S1HI (OFF_H1LO + ATILE)
#define OFF_S1LO (OFF_S1HI + ATILE)          // ends 131072
#define BSLICE   16384
#define OFF_BW2HI (OFF_S1LO + ATILE)
#define OFF_BW2LO (OFF_BW2HI + BSLICE)
#define OFF_BMHI  (OFF_BW2LO + BSLICE)
#define OFF_BMLO  (OFF_BMHI + BSLICE)        // ends 196608
#define OFF_W1    (OFF_BMLO + BSLICE)        // 9*128*4 = 4608
#define OFF_W3    (OFF_W1 + 4608)            // 4096
#define OFF_B1    (OFF_W3 + 4096)            // 512
#define OFF_B2    (OFF_B1 + 512)             // 512
#define OFF_B3    (OFF_B2 + 512)             // 64
#define OFF_REDU  (OFF_B3 + 64)              // 128 samples x 10 floats = 5120
#define SMEM_BYTES (OFF_REDU + 5120)

// ---------------- helpers ----------------
__device__ __forceinline__ float fast_tanh(float x) {
    float y; asm("tanh.approx.f32 %0, %1;" : "=f"(y) : "f"(x)); return y;
}
__device__ __forceinline__ ull pack2(float a, float b) {
    ull r; asm("mov.b64 %0, {%1,%2};" : "=l"(r) : "f"(a), "f"(b)); return r;
}
__device__ __forceinline__ float2 unpack2(ull v) {
    float2 f; asm("mov.b64 {%0,%1}, %2;" : "=f"(f.x), "=f"(f.y) : "l"(v)); return f;
}
__device__ __forceinline__ ull fma2(ull a, ull b, ull c) {
    ull r; asm("fma.rn.f32x2 %0, %1, %2, %3;" : "=l"(r) : "l"(a), "l"(b), "l"(c)); return r;
}
__device__ __forceinline__ ull add2(ull a, ull b) {
    ull r; asm("add.rn.f32x2 %0, %1, %2;" : "=l"(r) : "l"(a), "l"(b)); return r;
}
__device__ __forceinline__ void split_pack(float x0, float x1, uint& hi, uint& lo) {
    __nv_bfloat16 h0 = __float2bfloat16(x0);
    __nv_bfloat16 h1 = __float2bfloat16(x1);
    float r0 = x0 - __bfloat162float(h0);
    float r1 = x1 - __bfloat162float(h1);
    __nv_bfloat162 hp; hp.x = h0; hp.y = h1;
    __nv_bfloat162 lp; lp.x = __float2bfloat16(r0); lp.y = __float2bfloat16(r1);
    hi = *(uint*)&hp; lo = *(uint*)&lp;
}
__device__ __forceinline__ void mma_bf16(float* d, uint a0, uint a1, uint a2, uint a3,
                                         uint b0, uint b1) {
    asm("mma.sync.aligned.m16n8k16.row.col.f32.bf16.bf16.f32 "
        "{%0,%1,%2,%3},{%4,%5,%6,%7},{%8,%9},{%0,%1,%2,%3};"
        : "+f"(d[0]), "+f"(d[1]), "+f"(d[2]), "+f"(d[3])
        : "r"(a0), "r"(a1), "r"(a2), "r"(a3), "r"(b0), "r"(b1));
}

// ---------------- setup ----------------
__global__ void setup_kernel(const float* __restrict__ W1,
                             const float* __restrict__ W2,
                             const float* __restrict__ W3) {
    int idx = blockIdx.x * blockDim.x + threadIdx.x;   // 0..4095
    if (idx >= 16 * 8 * 32) return;
    int lane = idx & 31, s = (idx >> 5) & 7, jt = idx >> 8;
    int g = lane >> 2, c = lane & 3;
    int j = jt * 8 + g;
    int kb = s * 16 + c * 2;
    int ks[4] = {kb, kb + 1, kb + 8, kb + 9};
#pragma unroll
    for (int e = 0; e < 4; e++) {
        int k = ks[e];
        float w2 = W2[k * HD + j];
        float cc = 0.0f;
#pragma unroll
        for (int d = 0; d < DD; d++) cc += W1[d * HD + k] * W3[j * DD + d];
        float m = w2 * cc;
        __nv_bfloat16 whi = __float2bfloat16(w2);
        __nv_bfloat16 mhi = __float2bfloat16(m);
        int o = idx * 4 + e;
        g_bw2hi[o] = whi;
        g_bw2lo[o] = __float2bfloat16(w2 - __bfloat162float(whi));
        g_bmhi[o]  = mhi;
        g_bmlo[o]  = __float2bfloat16(m - __bfloat162float(mhi));
    }
}

// ---------------- main kernel ----------------
__global__ __launch_bounds__(TPB, 1)
void cnf_mma_kernel(const float* __restrict__ z,
                    const float* __restrict__ t,
                    const float* __restrict__ W1, const float* __restrict__ b1,
                    const float* __restrict__ b2, const float* __restrict__ b3,
                    const float* __restrict__ W3,
                    float* __restrict__ dz_out, float* __restrict__ dlogp_out,
                    int B)
{
    extern __shared__ __align__(16) char sm[];
    const int tid = threadIdx.x;
    const int wid = tid >> 5;
    const int lane = tid & 31;
    const int g = lane >> 2;
    const int c = lane & 3;
    const int bp = wid & 3;        // block-pair: covers m-blocks 2bp, 2bp+1
    const int jg = wid >> 2;       // jt quartet within half (0 or 1)

    float* W1s = (float*)(sm + OFF_W1);
    float* W3s = (float*)(sm + OFF_W3);
    float* b1s = (float*)(sm + OFF_B1);
    float* b2s = (float*)(sm + OFF_B2);
    float* b3s = (float*)(sm + OFF_B3);
    float* redu = (float*)(sm + OFF_REDU);

    // ---- stage misc + first B slice ----
    for (int i = tid; i < 9 * HD; i += TPB) W1s[i] = W1[i];
    for (int i = tid; i < HD * DD; i += TPB) W3s[i] = W3[i];
    if (tid < HD) { b1s[tid] = b1[tid]; b2s[tid] = b2[tid]; }
    if (tid < DD) b3s[tid] = b3[tid];
    {
        uint4* d0 = (uint4*)(sm + OFF_BW2HI);
        uint4* d1 = (uint4*)(sm + OFF_BW2LO);
        uint4* d2 = (uint4*)(sm + OFF_BMHI);
        uint4* d3 = (uint4*)(sm + OFF_BMLO);
        const uint4* s0 = (const uint4*)g_bw2hi;
        const uint4* s1 = (const uint4*)g_bw2lo;
        const uint4* s2 = (const uint4*)g_bmhi;
        const uint4* s3 = (const uint4*)g_bmlo;
        for (int i = tid; i < 1024; i += TPB) {
            d0[i] = s0[i]; d1[i] = s1[i]; d2[i] = s2[i]; d3[i] = s3[i];
        }
    }
    __syncthreads();

    // ---- layer 1: thread = (sample s_loc, k-half kh); 64 h1 values; permuted scatter ----
    {
        const int s_loc = tid & 127;
        const int kh = tid >> 7;
        const int sample0 = blockIdx.x * SPB + s_loc;
        float zr[DD];
        if (sample0 < B) {
            const float4* zv = (const float4*)(z + (size_t)sample0 * DD);
            float4 za = zv[0], zb = zv[1];
            zr[0]=za.x; zr[1]=za.y; zr[2]=za.z; zr[3]=za.w;
            zr[4]=zb.x; zr[5]=zb.y; zr[6]=zb.z; zr[7]=zb.w;
        } else {
#pragma unroll
            for (int d = 0; d < DD; d++) zr[d] = 0.0f;
        }
        const float tv = t[0];
        float h[64];
        const int kbase = kh * 64;
#pragma unroll
        for (int kk = 0; kk < 64; kk += 4) {
            float4 acc = *(const float4*)&b1s[kbase + kk];
#pragma unroll
            for (int d = 0; d < DD; d++) {
                float4 w = *(const float4*)&W1s[d * HD + kbase + kk];
                acc.x = fmaf(zr[d], w.x, acc.x);
                acc.y = fmaf(zr[d], w.y, acc.y);
                acc.z = fmaf(zr[d], w.z, acc.z);
                acc.w = fmaf(zr[d], w.w, acc.w);
            }
            float4 w8 = *(const float4*)&W1s[8 * HD + kbase + kk];
            h[kk + 0] = fast_tanh(fmaf(tv, w8.x, acc.x));
            h[kk + 1] = fast_tanh(fmaf(tv, w8.y, acc.y));
            h[kk + 2] = fast_tanh(fmaf(tv, w8.z, acc.z));
            h[kk + 3] = fast_tanh(fmaf(tv, w8.w, acc.w));
        }
        // permuted fragment scatter: frag f = g_a*4 + cc lives at loc = cc*8 + g_a
        const int blk_a = s_loc >> 4;
        const int rowin = s_loc & 15;
        const int g_a = rowin & 7;
        const int regrow = rowin >> 3;
#pragma unroll
        for (int i = 0; i < 32; i++) {
            const int kp = kh * 32 + i;
            const int s  = kp >> 3;
            const int w8 = kp & 7;
            const int cc = w8 & 3;
            const int reg = ((w8 >> 2) << 1) + regrow;
            const uint32_t off = (uint32_t)((((blk_a * 8 + s) * 32) + cc * 8 + g_a) * 16 + reg * 4);
            float x0 = h[2 * i], x1 = h[2 * i + 1];
            uint hi, lo;
            split_pack(x0, x1, hi, lo);
            *(uint*)(sm + OFF_H1HI + off) = hi;
            *(uint*)(sm + OFF_H1LO + off) = lo;
            float q0 = fmaf(-x0, x0, 1.0f);
            float q1 = fmaf(-x1, x1, 1.0f);
            split_pack(q0, q1, hi, lo);
            *(uint*)(sm + OFF_S1HI + off) = hi;
            *(uint*)(sm + OFF_S1LO + off) = lo;
        }
    }
    __syncthreads();

    // ---- GEMMs: warp covers 2 m-blocks x 4 jt per half ----
    const uint32_t aloc = (uint32_t)(((lane & 3) * 8 + (lane >> 2)) * 16);
    ull dz[2][2][4];     // [bb][row(g / g+8)][dpair]
    float tr[2][2] = {{0.f, 0.f}, {0.f, 0.f}};
#pragma unroll
    for (int bb = 0; bb < 2; bb++)
#pragma unroll
        for (int r = 0; r < 2; r++)
#pragma unroll
            for (int e = 0; e < 4; e++) dz[bb][r][e] = 0ULL;

#pragma unroll 1
    for (int nh = 0; nh < 2; nh++) {
        if (nh == 1) {
            __syncthreads();
            uint4* d0 = (uint4*)(sm + OFF_BW2HI);
            uint4* d1 = (uint4*)(sm + OFF_BW2LO);
            uint4* d2 = (uint4*)(sm + OFF_BMHI);
            uint4* d3 = (uint4*)(sm + OFF_BMLO);
            const uint4* s0 = (const uint4*)g_bw2hi + 1024;
            const uint4* s1 = (const uint4*)g_bw2lo + 1024;
            const uint4* s2 = (const uint4*)g_bmhi + 1024;
            const uint4* s3 = (const uint4*)g_bmlo + 1024;
            for (int i = tid; i < 1024; i += TPB) {
                d0[i] = s0[i]; d1[i] = s1[i]; d2[i] = s2[i]; d3[i] = s3[i];
            }
            __syncthreads();
        }

        float acc1[2][4][4], acc2[2][4][4];
#pragma unroll
        for (int bb = 0; bb < 2; bb++)
#pragma unroll
            for (int q = 0; q < 4; q++)
#pragma unroll
                for (int e = 0; e < 4; e++) { acc1[bb][q][e] = 0.0f; acc2[bb][q][e] = 0.0f; }

#pragma unroll
        for (int s = 0; s < 8; s++) {
            uint4 h1h[2], h1l[2], s1h[2], s1l[2];
#pragma unroll
            for (int bb = 0; bb < 2; bb++) {
                const uint32_t ao = (uint32_t)(((2 * bp + bb) * 8 + s) * 512) + aloc;
                h1h[bb] = *(const uint4*)(sm + OFF_H1HI + ao);
                h1l[bb] = *(const uint4*)(sm + OFF_H1LO + ao);
                s1h[bb] = *(const uint4*)(sm + OFF_S1HI + ao);
                s1l[bb] = *(const uint4*)(sm + OFF_S1LO + ao);
            }
#pragma unroll
            for (int q = 0; q < 4; q++) {
                const int bo = (((jg * 4 + q) * 8 + s) * 32 + lane) * 8;
                uint2 wh = *(const uint2*)(sm + OFF_BW2HI + bo);
                uint2 wl = *(const uint2*)(sm + OFF_BW2LO + bo);
                uint2 mh = *(const uint2*)(sm + OFF_BMHI + bo);
                uint2 ml = *(const uint2*)(sm + OFF_BMLO + bo);
#pragma unroll
                for (int bb = 0; bb < 2; bb++) {
                    mma_bf16(acc1[bb][q], h1h[bb].x, h1h[bb].y, h1h[bb].z, h1h[bb].w, wh.x, wh.y);
                    mma_bf16(acc1[bb][q], h1h[bb].x, h1h[bb].y, h1h[bb].z, h1h[bb].w, wl.x, wl.y);
                    mma_bf16(acc1[bb][q], h1l[bb].x, h1l[bb].y, h1l[bb].z, h1l[bb].w, wh.x, wh.y);
                    mma_bf16(acc2[bb][q], s1h[bb].x, s1h[bb].y, s1h[bb].z, s1h[bb].w, mh.x, mh.y);
                    mma_bf16(acc2[bb][q], s1h[bb].x, s1h[bb].y, s1h[bb].z, s1h[bb].w, ml.x, ml.y);
                    mma_bf16(acc2[bb][q], s1l[bb].x, s1l[bb].y, s1l[bb].z, s1l[bb].w, mh.x, mh.y);
                }
            }
        }

        // ---- epilogue for this half ----
#pragma unroll
        for (int q = 0; q < 4; q++) {
            const int j0 = (nh * 8 + jg * 4 + q) * 8 + 2 * c;
            const float b2x = b2s[j0], b2y = b2s[j0 + 1];
            const ull* w30 = (const ull*)(W3s + j0 * DD);
            const ull* w31 = (const ull*)(W3s + (j0 + 1) * DD);
#pragma unroll
            for (int bb = 0; bb < 2; bb++) {
                {
                    float h2 = fast_tanh(acc1[bb][q][0] + b2x);
                    tr[bb][0] = fmaf(acc2[bb][q][0], fmaf(-h2, h2, 1.0f), tr[bb][0]);
                    ull hp = pack2(h2, h2);
                    dz[bb][0][0] = fma2(hp, w30[0], dz[bb][0][0]);
                    dz[bb][0][1] = fma2(hp, w30[1], dz[bb][0][1]);
                    dz[bb][0][2] = fma2(hp, w30[2], dz[bb][0][2]);
                    dz[bb][0][3] = fma2(hp, w30[3], dz[bb][0][3]);
                }
                {
                    float h2 = fast_tanh(acc1[bb][q][1] + b2y);
                    tr[bb][0] = fmaf(acc2[bb][q][1], fmaf(-h2, h2, 1.0f), tr[bb][0]);
                    ull hp = pack2(h2, h2);
                    dz[bb][0][0] = fma2(hp, w31[0], dz[bb][0][0]);
                    dz[bb][0][1] = fma2(hp, w31[1], dz[bb][0][1]);
                    dz[bb][0][2] = fma2(hp, w31[2], dz[bb][0][2]);
                    dz[bb][0][3] = fma2(hp, w31[3], dz[bb][0][3]);
                }
                {
                    float h2 = fast_tanh(acc1[bb][q][2] + b2x);
                    tr[bb][1] = fmaf(acc2[bb][q][2], fmaf(-h2, h2, 1.0f), tr[bb][1]);
                    ull hp = pack2(h2, h2);
                    dz[bb][1][0] = fma2(hp, w30[0], dz[bb][1][0]);
                    dz[bb][1][1] = fma2(hp, w30[1], dz[bb][1][1]);
                    dz[bb][1][2] = fma2(hp, w30[2], dz[bb][1][2]);
                    dz[bb][1][3] = fma2(hp, w30[3], dz[bb][1][3]);
                }
                {
                    float h2 = fast_tanh(acc1[bb][q][3] + b2y);
                    tr[bb][1] = fmaf(acc2[bb][q][3], fmaf(-h2, h2, 1.0f), tr[bb][1]);
                    ull hp = pack2(h2, h2);
                    dz[bb][1][0] = fma2(hp, w31[0], dz[bb][1][0]);
                    dz[bb][1][1] = fma2(hp, w31[1], dz[bb][1][1]);
                    dz[bb][1][2] = fma2(hp, w31[2], dz[bb][1][2]);
                    dz[bb][1][3] = fma2(hp, w31[3], dz[bb][1][3]);
                }
            }
        }
    }

    // ---- reduce over the 4 c-lanes ----
#pragma unroll
    for (int off = 1; off <= 2; off <<= 1) {
#pragma unroll
        for (int bb = 0; bb < 2; bb++)
#pragma unroll
            for (int r = 0; r < 2; r++) {
                tr[bb][r] += __shfl_xor_sync(0xffffffffu, tr[bb][r], off);
#pragma unroll
                for (int e = 0; e < 4; e++)
                    dz[bb][r][e] = add2(dz[bb][r][e], __shfl_xor_sync(0xffffffffu, dz[bb][r][e], off));
            }
    }

    // ---- cross-warp combine (jg=0 stages, jg=1 finishes) ----
    __syncthreads();
    if (jg == 0 && c == 0) {
#pragma unroll
        for (int bb = 0; bb < 2; bb++)
#pragma unroll
            for (int r = 0; r < 2; r++) {
                const int sl = (2 * bp + bb) * 16 + r * 8 + g;
                float* rp = redu + sl * 10;
                float2 v;
                v = unpack2(dz[bb][r][0]); rp[0] = v.x; rp[1] = v.y;
                v = unpack2(dz[bb][r][1]); rp[2] = v.x; rp[3] = v.y;
                v = unpack2(dz[bb][r][2]); rp[4] = v.x; rp[5] = v.y;
                v = unpack2(dz[bb][r][3]); rp[6] = v.x; rp[7] = v.y;
                rp[8] = tr[bb][r];
            }
    }
    __syncthreads();
    if (jg == 1 && c == 0) {
        float4 b3a = *(const float4*)&b3s[0];
        float4 b3b = *(const float4*)&b3s[4];
#pragma unroll
        for (int bb = 0; bb < 2; bb++)
#pragma unroll
            for (int r = 0; r < 2; r++) {
                const int sl = (2 * bp + bb) * 16 + r * 8 + g;
                const int sample = blockIdx.x * SPB + sl;
                const float* rp = redu + sl * 10;
                float2 v0 = unpack2(dz[bb][r][0]), v1 = unpack2(dz[bb][r][1]);
                float2 v2 = unpack2(dz[bb][r][2]), v3 = unpack2(dz[bb][r][3]);
                if (sample < B) {
                    float4* ov = (float4*)(dz_out + (size_t)sample * DD);
                    ov[0] = make_float4(v0.x + rp[0] + b3a.x, v0.y + rp[1] + b3a.y,
                                        v1.x + rp[2] + b3a.z, v1.y + rp[3] + b3a.w);
                    ov[1] = make_float4(v2.x + rp[4] + b3b.x, v2.y + rp[5] + b3b.y,
                                        v3.x + rp[6] + b3b.z, v3.y + rp[7] + b3b.w);
                    dlogp_out[sample] = -(tr[bb][r] + rp[8]);
                }
            }
    }
}

extern "C" void kernel_launch(void* const* d_in, const int* in_sizes, int n_in,
                              void* d_out, int out_size) {
    const float* z  = (const float*)d_in[0];
    // d_in[1] = logp_z (unused: dlogp/dt = -trace only)
    const float* t  = (const float*)d_in[2];
    const float* W1 = (const float*)d_in[3];
    const float* b1 = (const float*)d_in[4];
    const float* W2 = (const float*)d_in[5];
    const float* b2 = (const float*)d_in[6];
    const float* W3 = (const float*)d_in[7];
    const float* b3 = (const float*)d_in[8];

    const int B = in_sizes[0] / DD;
    float* dz_out    = (float*)d_out;
    float* dlogp_out = dz_out + (size_t)B * DD;

    setup_kernel<<<16, 256>>>(W1, W2, W3);

    cudaFuncSetAttribute(cnf_mma_kernel,
                         cudaFuncAttributeMaxDynamicSharedMemorySize, SMEM_BYTES);
    cnf_mma_kernel<<<(B + SPB - 1) / SPB, TPB, SMEM_BYTES>>>(
        z, t, W1, b1, b2, b3, W3, dz_out, dlogp_out, B);
}

// round 8
// speedup vs baseline: 1.3628x; 1.2452x over previous
#include <cuda_runtime.h>
#include <cuda_bf16.h>
#include <cstdint>
#include <math.h>

#define HD 128
#define DD 8
#define TPB 256
#define SPB 128

typedef unsigned long long ull;
typedef unsigned int uint;

// B operands in per-lane mma-fragment order: [jt(16)][s(8)][lane(32)] x 4 bf16 (8B/lane)
__device__ __align__(16) __nv_bfloat16 g_bw2hi[16 * 8 * 32 * 4];
__device__ __align__(16) __nv_bfloat16 g_bw2lo[16 * 8 * 32 * 4];
__device__ __align__(16) __nv_bfloat16 g_bmhi[16 * 8 * 32 * 4];
__device__ __align__(16) __nv_bfloat16 g_bmlo[16 * 8 * 32 * 4];

// ---------------- smem layout (bytes) ----------------
// A tiles fragment-packed with two-sided conflict-free permutation:
// [blk(8)][s(8)][loc(32)][16B]  where loc(g,c) = (g XOR (c<<1)) | (c<<3)
#define ATILE 32768
#define OFF_H1HI 0
#define OFF_H1LO (OFF_H1HI + ATILE)
#define OFF_S1HI (OFF_H1LO + ATILE)
#define OFF_S1LO (OFF_S1HI + ATILE)          // ends 131072
#define BSLICE   16384
#define OFF_BW2HI (OFF_S1LO + ATILE)
#define OFF_BW2LO (OFF_BW2HI + BSLICE)
#define OFF_BMHI  (OFF_BW2LO + BSLICE)
#define OFF_BMLO  (OFF_BMHI + BSLICE)        // ends 196608
#define OFF_W1    (OFF_BMLO + BSLICE)        // 9*128*4 = 4608
#define OFF_W3    (OFF_W1 + 4608)            // 4096
#define OFF_B1    (OFF_W3 + 4096)            // 512
#define OFF_B2    (OFF_B1 + 512)             // 512
#define OFF_B3    (OFF_B2 + 512)             // 64
#define OFF_REDU  (OFF_B3 + 64)              // 128 samples x 10 floats = 5120
#define SMEM_BYTES (OFF_REDU + 5120)

// ---------------- helpers ----------------
__device__ __forceinline__ float fast_tanh(float x) {
    float y; asm("tanh.approx.f32 %0, %1;" : "=f"(y) : "f"(x)); return y;
}
__device__ __forceinline__ ull pack2(float a, float b) {
    ull r; asm("mov.b64 %0, {%1,%2};" : "=l"(r) : "f"(a), "f"(b)); return r;
}
__device__ __forceinline__ float2 unpack2(ull v) {
    float2 f; asm("mov.b64 {%0,%1}, %2;" : "=f"(f.x), "=f"(f.y) : "l"(v)); return f;
}
__device__ __forceinline__ ull fma2(ull a, ull b, ull c) {
    ull r; asm("fma.rn.f32x2 %0, %1, %2, %3;" : "=l"(r) : "l"(a), "l"(b), "l"(c)); return r;
}
__device__ __forceinline__ ull add2(ull a, ull b) {
    ull r; asm("add.rn.f32x2 %0, %1, %2;" : "=l"(r) : "l"(a), "l"(b)); return r;
}
__device__ __forceinline__ void split_pack(float x0, float x1, uint& hi, uint& lo) {
    __nv_bfloat16 h0 = __float2bfloat16(x0);
    __nv_bfloat16 h1 = __float2bfloat16(x1);
    float r0 = x0 - __bfloat162float(h0);
    float r1 = x1 - __bfloat162float(h1);
    __nv_bfloat162 hp; hp.x = h0; hp.y = h1;
    __nv_bfloat162 lp; lp.x = __float2bfloat16(r0); lp.y = __float2bfloat16(r1);
    hi = *(uint*)&hp; lo = *(uint*)&lp;
}
__device__ __forceinline__ void mma_bf16(float* d, uint a0, uint a1, uint a2, uint a3,
                                         uint b0, uint b1) {
    asm("mma.sync.aligned.m16n8k16.row.col.f32.bf16.bf16.f32 "
        "{%0,%1,%2,%3},{%4,%5,%6,%7},{%8,%9},{%0,%1,%2,%3};"
        : "+f"(d[0]), "+f"(d[1]), "+f"(d[2]), "+f"(d[3])
        : "r"(a0), "r"(a1), "r"(a2), "r"(a3), "r"(b0), "r"(b1));
}

// ---------------- setup ----------------
__global__ void setup_kernel(const float* __restrict__ W1,
                             const float* __restrict__ W2,
                             const float* __restrict__ W3) {
    int idx = blockIdx.x * blockDim.x + threadIdx.x;   // 0..4095
    if (idx >= 16 * 8 * 32) return;
    int lane = idx & 31, s = (idx >> 5) & 7, jt = idx >> 8;
    int g = lane >> 2, c = lane & 3;
    int j = jt * 8 + g;
    int kb = s * 16 + c * 2;
    int ks[4] = {kb, kb + 1, kb + 8, kb + 9};
#pragma unroll
    for (int e = 0; e < 4; e++) {
        int k = ks[e];
        float w2 = W2[k * HD + j];
        float cc = 0.0f;
#pragma unroll
        for (int d = 0; d < DD; d++) cc += W1[d * HD + k] * W3[j * DD + d];
        float m = w2 * cc;
        __nv_bfloat16 whi = __float2bfloat16(w2);
        __nv_bfloat16 mhi = __float2bfloat16(m);
        int o = idx * 4 + e;
        g_bw2hi[o] = whi;
        g_bw2lo[o] = __float2bfloat16(w2 - __bfloat162float(whi));
        g_bmhi[o]  = mhi;
        g_bmlo[o]  = __float2bfloat16(m - __bfloat162float(mhi));
    }
}

// ---------------- main kernel ----------------
__global__ __launch_bounds__(TPB, 1)
void cnf_mma_kernel(const float* __restrict__ z,
                    const float* __restrict__ t,
                    const float* __restrict__ W1, const float* __restrict__ b1,
                    const float* __restrict__ b2, const float* __restrict__ b3,
                    const float* __restrict__ W3,
                    float* __restrict__ dz_out, float* __restrict__ dlogp_out,
                    int B)
{
    extern __shared__ __align__(16) char sm[];
    const int tid = threadIdx.x;
    const int wid = tid >> 5;
    const int lane = tid & 31;
    const int g = lane >> 2;
    const int c = lane & 3;
    const int bp = wid & 3;        // block-pair: covers m-blocks 2bp, 2bp+1
    const int jg = wid >> 2;       // jt quartet within half (0 or 1)

    float* W1s = (float*)(sm + OFF_W1);
    float* W3s = (float*)(sm + OFF_W3);
    float* b1s = (float*)(sm + OFF_B1);
    float* b2s = (float*)(sm + OFF_B2);
    float* b3s = (float*)(sm + OFF_B3);
    float* redu = (float*)(sm + OFF_REDU);

    // ---- stage misc + first B slice ----
    for (int i = tid; i < 9 * HD; i += TPB) W1s[i] = W1[i];
    for (int i = tid; i < HD * DD; i += TPB) W3s[i] = W3[i];
    if (tid < HD) { b1s[tid] = b1[tid]; b2s[tid] = b2[tid]; }
    if (tid < DD) b3s[tid] = b3[tid];
    {
        uint4* d0 = (uint4*)(sm + OFF_BW2HI);
        uint4* d1 = (uint4*)(sm + OFF_BW2LO);
        uint4* d2 = (uint4*)(sm + OFF_BMHI);
        uint4* d3 = (uint4*)(sm + OFF_BMLO);
        const uint4* s0 = (const uint4*)g_bw2hi;
        const uint4* s1 = (const uint4*)g_bw2lo;
        const uint4* s2 = (const uint4*)g_bmhi;
        const uint4* s3 = (const uint4*)g_bmlo;
        for (int i = tid; i < 1024; i += TPB) {
            d0[i] = s0[i]; d1[i] = s1[i]; d2[i] = s2[i]; d3[i] = s3[i];
        }
    }
    __syncthreads();

    // ---- layer 1: thread = (sample s_loc, k-half kh); 64 h1 values; permuted scatter ----
    {
        const int s_loc = tid & 127;
        const int kh = tid >> 7;
        const int sample0 = blockIdx.x * SPB + s_loc;
        float zr[DD];
        if (sample0 < B) {
            const float4* zv = (const float4*)(z + (size_t)sample0 * DD);
            float4 za = zv[0], zb = zv[1];
            zr[0]=za.x; zr[1]=za.y; zr[2]=za.z; zr[3]=za.w;
            zr[4]=zb.x; zr[5]=zb.y; zr[6]=zb.z; zr[7]=zb.w;
        } else {
#pragma unroll
            for (int d = 0; d < DD; d++) zr[d] = 0.0f;
        }
        const float tv = t[0];
        float h[64];
        const int kbase = kh * 64;
#pragma unroll
        for (int kk = 0; kk < 64; kk += 4) {
            float4 acc = *(const float4*)&b1s[kbase + kk];
#pragma unroll
            for (int d = 0; d < DD; d++) {
                float4 w = *(const float4*)&W1s[d * HD + kbase + kk];
                acc.x = fmaf(zr[d], w.x, acc.x);
                acc.y = fmaf(zr[d], w.y, acc.y);
                acc.z = fmaf(zr[d], w.z, acc.z);
                acc.w = fmaf(zr[d], w.w, acc.w);
            }
            float4 w8 = *(const float4*)&W1s[8 * HD + kbase + kk];
            h[kk + 0] = fast_tanh(fmaf(tv, w8.x, acc.x));
            h[kk + 1] = fast_tanh(fmaf(tv, w8.y, acc.y));
            h[kk + 2] = fast_tanh(fmaf(tv, w8.z, acc.z));
            h[kk + 3] = fast_tanh(fmaf(tv, w8.w, acc.w));
        }
        // two-sided conflict-free scatter: frag (g_a, cc) lives at loc = (g_a ^ (cc<<1)) | (cc<<3)
        const int blk_a = s_loc >> 4;
        const int rowin = s_loc & 15;
        const int g_a = rowin & 7;
        const int regrow = rowin >> 3;
#pragma unroll
        for (int i = 0; i < 32; i++) {
            const int kp = kh * 32 + i;
            const int s  = kp >> 3;
            const int w8 = kp & 7;
            const int cc = w8 & 3;
            const int reg = ((w8 >> 2) << 1) + regrow;
            const int loc = (g_a ^ (cc << 1)) | (cc << 3);
            const uint32_t off = (uint32_t)((((blk_a * 8 + s) * 32) + loc) * 16 + reg * 4);
            float x0 = h[2 * i], x1 = h[2 * i + 1];
            uint hi, lo;
            split_pack(x0, x1, hi, lo);
            *(uint*)(sm + OFF_H1HI + off) = hi;
            *(uint*)(sm + OFF_H1LO + off) = lo;
            float q0 = fmaf(-x0, x0, 1.0f);
            float q1 = fmaf(-x1, x1, 1.0f);
            split_pack(q0, q1, hi, lo);
            *(uint*)(sm + OFF_S1HI + off) = hi;
            *(uint*)(sm + OFF_S1LO + off) = lo;
        }
    }
    __syncthreads();

    // ---- GEMMs: warp covers 2 m-blocks x 4 jt per half ----
    const uint32_t aloc = (uint32_t)((((g ^ (c << 1)) | (c << 3)) * 16));
    ull dz[2][2][4];     // [bb][row(g / g+8)][dpair]
    float tr[2][2] = {{0.f, 0.f}, {0.f, 0.f}};
#pragma unroll
    for (int bb = 0; bb < 2; bb++)
#pragma unroll
        for (int r = 0; r < 2; r++)
#pragma unroll
            for (int e = 0; e < 4; e++) dz[bb][r][e] = 0ULL;

#pragma unroll 1
    for (int nh = 0; nh < 2; nh++) {
        if (nh == 1) {
            __syncthreads();
            uint4* d0 = (uint4*)(sm + OFF_BW2HI);
            uint4* d1 = (uint4*)(sm + OFF_BW2LO);
            uint4* d2 = (uint4*)(sm + OFF_BMHI);
            uint4* d3 = (uint4*)(sm + OFF_BMLO);
            const uint4* s0 = (const uint4*)g_bw2hi + 1024;
            const uint4* s1 = (const uint4*)g_bw2lo + 1024;
            const uint4* s2 = (const uint4*)g_bmhi + 1024;
            const uint4* s3 = (const uint4*)g_bmlo + 1024;
            for (int i = tid; i < 1024; i += TPB) {
                d0[i] = s0[i]; d1[i] = s1[i]; d2[i] = s2[i]; d3[i] = s3[i];
            }
            __syncthreads();
        }

        float acc1[2][4][4], acc2[2][4][4];
#pragma unroll
        for (int bb = 0; bb < 2; bb++)
#pragma unroll
            for (int q = 0; q < 4; q++)
#pragma unroll
                for (int e = 0; e < 4; e++) { acc1[bb][q][e] = 0.0f; acc2[bb][q][e] = 0.0f; }

#pragma unroll
        for (int s = 0; s < 8; s++) {
            uint4 h1h[2], h1l[2], s1h[2], s1l[2];
#pragma unroll
            for (int bb = 0; bb < 2; bb++) {
                const uint32_t ao = (uint32_t)(((2 * bp + bb) * 8 + s) * 512) + aloc;
                h1h[bb] = *(const uint4*)(sm + OFF_H1HI + ao);
                h1l[bb] = *(const uint4*)(sm + OFF_H1LO + ao);
                s1h[bb] = *(const uint4*)(sm + OFF_S1HI + ao);
                s1l[bb] = *(const uint4*)(sm + OFF_S1LO + ao);
            }
#pragma unroll
            for (int q = 0; q < 4; q++) {
                const int bo = (((jg * 4 + q) * 8 + s) * 32 + lane) * 8;
                uint2 wh = *(const uint2*)(sm + OFF_BW2HI + bo);
                uint2 wl = *(const uint2*)(sm + OFF_BW2LO + bo);
                uint2 mh = *(const uint2*)(sm + OFF_BMHI + bo);
                uint2 ml = *(const uint2*)(sm + OFF_BMLO + bo);
#pragma unroll
                for (int bb = 0; bb < 2; bb++) {
                    mma_bf16(acc1[bb][q], h1h[bb].x, h1h[bb].y, h1h[bb].z, h1h[bb].w, wh.x, wh.y);
                    mma_bf16(acc1[bb][q], h1h[bb].x, h1h[bb].y, h1h[bb].z, h1h[bb].w, wl.x, wl.y);
                    mma_bf16(acc1[bb][q], h1l[bb].x, h1l[bb].y, h1l[bb].z, h1l[bb].w, wh.x, wh.y);
                    mma_bf16(acc2[bb][q], s1h[bb].x, s1h[bb].y, s1h[bb].z, s1h[bb].w, mh.x, mh.y);
                    mma_bf16(acc2[bb][q], s1h[bb].x, s1h[bb].y, s1h[bb].z, s1h[bb].w, ml.x, ml.y);
                    mma_bf16(acc2[bb][q], s1l[bb].x, s1l[bb].y, s1l[bb].z, s1l[bb].w, mh.x, mh.y);
                }
            }
        }

        // ---- epilogue for this half ----
#pragma unroll
        for (int q = 0; q < 4; q++) {
            const int j0 = (nh * 8 + jg * 4 + q) * 8 + 2 * c;
            const float b2x = b2s[j0], b2y = b2s[j0 + 1];
            const ull* w30 = (const ull*)(W3s + j0 * DD);
            const ull* w31 = (const ull*)(W3s + (j0 + 1) * DD);
#pragma unroll
            for (int bb = 0; bb < 2; bb++) {
                {
                    float h2 = fast_tanh(acc1[bb][q][0] + b2x);
                    tr[bb][0] = fmaf(acc2[bb][q][0], fmaf(-h2, h2, 1.0f), tr[bb][0]);
                    ull hp = pack2(h2, h2);
                    dz[bb][0][0] = fma2(hp, w30[0], dz[bb][0][0]);
                    dz[bb][0][1] = fma2(hp, w30[1], dz[bb][0][1]);
                    dz[bb][0][2] = fma2(hp, w30[2], dz[bb][0][2]);
                    dz[bb][0][3] = fma2(hp, w30[3], dz[bb][0][3]);
                }
                {
                    float h2 = fast_tanh(acc1[bb][q][1] + b2y);
                    tr[bb][0] = fmaf(acc2[bb][q][1], fmaf(-h2, h2, 1.0f), tr[bb][0]);
                    ull hp = pack2(h2, h2);
                    dz[bb][0][0] = fma2(hp, w31[0], dz[bb][0][0]);
                    dz[bb][0][1] = fma2(hp, w31[1], dz[bb][0][1]);
                    dz[bb][0][2] = fma2(hp, w31[2], dz[bb][0][2]);
                    dz[bb][0][3] = fma2(hp, w31[3], dz[bb][0][3]);
                }
                {
                    float h2 = fast_tanh(acc1[bb][q][2] + b2x);
                    tr[bb][1] = fmaf(acc2[bb][q][2], fmaf(-h2, h2, 1.0f), tr[bb][1]);
                    ull hp = pack2(h2, h2);
                    dz[bb][1][0] = fma2(hp, w30[0], dz[bb][1][0]);
                    dz[bb][1][1] = fma2(hp, w30[1], dz[bb][1][1]);
                    dz[bb][1][2] = fma2(hp, w30[2], dz[bb][1][2]);
                    dz[bb][1][3] = fma2(hp, w30[3], dz[bb][1][3]);
                }
                {
                    float h2 = fast_tanh(acc1[bb][q][3] + b2y);
                    tr[bb][1] = fmaf(acc2[bb][q][3], fmaf(-h2, h2, 1.0f), tr[bb][1]);
                    ull hp = pack2(h2, h2);
                    dz[bb][1][0] = fma2(hp, w31[0], dz[bb][1][0]);
                    dz[bb][1][1] = fma2(hp, w31[1], dz[bb][1][1]);
                    dz[bb][1][2] = fma2(hp, w31[2], dz[bb][1][2]);
                    dz[bb][1][3] = fma2(hp, w31[3], dz[bb][1][3]);
                }
            }
        }
    }

    // ---- reduce over the 4 c-lanes ----
#pragma unroll
    for (int off = 1; off <= 2; off <<= 1) {
#pragma unroll
        for (int bb = 0; bb < 2; bb++)
#pragma unroll
            for (int r = 0; r < 2; r++) {
                tr[bb][r] += __shfl_xor_sync(0xffffffffu, tr[bb][r], off);
#pragma unroll
                for (int e = 0; e < 4; e++)
                    dz[bb][r][e] = add2(dz[bb][r][e], __shfl_xor_sync(0xffffffffu, dz[bb][r][e], off));
            }
    }

    // ---- cross-warp combine (jg=0 stages, jg=1 finishes) ----
    __syncthreads();
    if (jg == 0 && c == 0) {
#pragma unroll
        for (int bb = 0; bb < 2; bb++)
#pragma unroll
            for (int r = 0; r < 2; r++) {
                const int sl = (2 * bp + bb) * 16 + r * 8 + g;
                float* rp = redu + sl * 10;
                float2 v;
                v = unpack2(dz[bb][r][0]); rp[0] = v.x; rp[1] = v.y;
                v = unpack2(dz[bb][r][1]); rp[2] = v.x; rp[3] = v.y;
                v = unpack2(dz[bb][r][2]); rp[4] = v.x; rp[5] = v.y;
                v = unpack2(dz[bb][r][3]); rp[6] = v.x; rp[7] = v.y;
                rp[8] = tr[bb][r];
            }
    }
    __syncthreads();
    if (jg == 1 && c == 0) {
        float4 b3a = *(const float4*)&b3s[0];
        float4 b3b = *(const float4*)&b3s[4];
#pragma unroll
        for (int bb = 0; bb < 2; bb++)
#pragma unroll
            for (int r = 0; r < 2; r++) {
                const int sl = (2 * bp + bb) * 16 + r * 8 + g;
                const int sample = blockIdx.x * SPB + sl;
                const float* rp = redu + sl * 10;
                float2 v0 = unpack2(dz[bb][r][0]), v1 = unpack2(dz[bb][r][1]);
                float2 v2 = unpack2(dz[bb][r][2]), v3 = unpack2(dz[bb][r][3]);
                if (sample < B) {
                    float4* ov = (float4*)(dz_out + (size_t)sample * DD);
                    ov[0] = make_float4(v0.x + rp[0] + b3a.x, v0.y + rp[1] + b3a.y,
                                        v1.x + rp[2] + b3a.z, v1.y + rp[3] + b3a.w);
                    ov[1] = make_float4(v2.x + rp[4] + b3b.x, v2.y + rp[5] + b3b.y,
                                        v3.x + rp[6] + b3b.z, v3.y + rp[7] + b3b.w);
                    dlogp_out[sample] = -(tr[bb][r] + rp[8]);
                }
            }
    }
}

extern "C" void kernel_launch(void* const* d_in, const int* in_sizes, int n_in,
                              void* d_out, int out_size) {
    const float* z  = (const float*)d_in[0];
    // d_in[1] = logp_z (unused: dlogp/dt = -trace only)
    const float* t  = (const float*)d_in[2];
    const float* W1 = (const float*)d_in[3];
    const float* b1 = (const float*)d_in[4];
    const float* W2 = (const float*)d_in[5];
    const float* b2 = (const float*)d_in[6];
    const float* W3 = (const float*)d_in[7];
    const float* b3 = (const float*)d_in[8];

    const int B = in_sizes[0] / DD;
    float* dz_out    = (float*)d_out;
    float* dlogp_out = dz_out + (size_t)B * DD;

    setup_kernel<<<16, 256>>>(W1, W2, W3);

    cudaFuncSetAttribute(cnf_mma_kernel,
                         cudaFuncAttributeMaxDynamicSharedMemorySize, SMEM_BYTES);
    cnf_mma_kernel<<<(B + SPB - 1) / SPB, TPB, SMEM_BYTES>>>(
        z, t, W1, b1, b2, b3, W3, dz_out, dlogp_out, B);
}

// round 9
// speedup vs baseline: 1.6114x; 1.1824x over previous
#include <cuda_runtime.h>
#include <cuda_bf16.h>
#include <cstdint>

#define HD 128
#define DD 8
#define TPB 512
#define SPB 128

typedef unsigned long long ull;
typedef unsigned int uint;

// B fragments, one uint4 per (jt,s,lane): .x,.y = hi pair, .z,.w = lo pair
__device__ __align__(16) uint4 g_bw2[16 * 8 * 32];
__device__ __align__(16) uint4 g_bm [16 * 8 * 32];

// ---------------- smem layout (bytes) ----------------
// A tiles fragment-packed, two-sided conflict-free permutation:
// [blk(8)][s(8)][loc(32)][16B],  loc(g,c) = (g XOR (c<<1)) | (c<<3)
#define ATILE 32768
#define OFF_H1HI 0
#define OFF_H1LO (OFF_H1HI + ATILE)
#define OFF_S1HI (OFF_H1LO + ATILE)
#define OFF_S1LO (OFF_S1HI + ATILE)          // ends 131072
#define OFF_W1   (OFF_S1LO + ATILE)          // 9*128*4 = 4608
#define OFF_W3   (OFF_W1 + 4608)             // 4096
#define OFF_B1   (OFF_W3 + 4096)             // 512
#define OFF_B2   (OFF_B1 + 512)              // 512
#define OFF_B3   (OFF_B2 + 512)              // 64
#define OFF_REDU (OFF_B3 + 64)               // 128 samples x 3 slots x 10 floats
#define SMEM_BYTES (OFF_REDU + 128 * 30 * 4)

// ---------------- helpers ----------------
__device__ __forceinline__ float fast_tanh(float x) {
    float y; asm("tanh.approx.f32 %0, %1;" : "=f"(y) : "f"(x)); return y;
}
__device__ __forceinline__ ull pack2(float a, float b) {
    ull r; asm("mov.b64 %0, {%1,%2};" : "=l"(r) : "f"(a), "f"(b)); return r;
}
__device__ __forceinline__ float2 unpack2(ull v) {
    float2 f; asm("mov.b64 {%0,%1}, %2;" : "=f"(f.x), "=f"(f.y) : "l"(v)); return f;
}
__device__ __forceinline__ ull fma2(ull a, ull b, ull c) {
    ull r; asm("fma.rn.f32x2 %0, %1, %2, %3;" : "=l"(r) : "l"(a), "l"(b), "l"(c)); return r;
}
__device__ __forceinline__ ull add2(ull a, ull b) {
    ull r; asm("add.rn.f32x2 %0, %1, %2;" : "=l"(r) : "l"(a), "l"(b)); return r;
}
__device__ __forceinline__ void split_pack(float x0, float x1, uint& hi, uint& lo) {
    __nv_bfloat16 h0 = __float2bfloat16(x0);
    __nv_bfloat16 h1 = __float2bfloat16(x1);
    float r0 = x0 - __bfloat162float(h0);
    float r1 = x1 - __bfloat162float(h1);
    __nv_bfloat162 hp; hp.x = h0; hp.y = h1;
    __nv_bfloat162 lp; lp.x = __float2bfloat16(r0); lp.y = __float2bfloat16(r1);
    hi = *(uint*)&hp; lo = *(uint*)&lp;
}
__device__ __forceinline__ uint pack_bf(float a, float b) {
    __nv_bfloat162 p; p.x = __float2bfloat16(a); p.y = __float2bfloat16(b);
    return *(uint*)&p;
}
__device__ __forceinline__ void mma_bf16(float* d, uint a0, uint a1, uint a2, uint a3,
                                         uint b0, uint b1) {
    asm("mma.sync.aligned.m16n8k16.row.col.f32.bf16.bf16.f32 "
        "{%0,%1,%2,%3},{%4,%5,%6,%7},{%8,%9},{%0,%1,%2,%3};"
        : "+f"(d[0]), "+f"(d[1]), "+f"(d[2]), "+f"(d[3])
        : "r"(a0), "r"(a1), "r"(a2), "r"(a3), "r"(b0), "r"(b1));
}

// ---------------- setup ----------------
__global__ void setup_kernel(const float* __restrict__ W1,
                             const float* __restrict__ W2,
                             const float* __restrict__ W3) {
    int idx = blockIdx.x * blockDim.x + threadIdx.x;   // 0..4095 = (jt, s, lane)
    if (idx >= 16 * 8 * 32) return;
    int lane = idx & 31, s = (idx >> 5) & 7, jt = idx >> 8;
    int g = lane >> 2, c = lane & 3;
    int j = jt * 8 + g;
    int kb = s * 16 + c * 2;
    int ks[4] = {kb, kb + 1, kb + 8, kb + 9};
    float w2v[4], mv[4];
#pragma unroll
    for (int e = 0; e < 4; e++) {
        int k = ks[e];
        float w2 = W2[k * HD + j];
        float cc = 0.0f;
#pragma unroll
        for (int d = 0; d < DD; d++) cc += W1[d * HD + k] * W3[j * DD + d];
        w2v[e] = w2;
        mv[e]  = w2 * cc;
    }
    float w2hi[4], mhi[4];
#pragma unroll
    for (int e = 0; e < 4; e++) {
        w2hi[e] = __bfloat162float(__float2bfloat16(w2v[e]));
        mhi[e]  = __bfloat162float(__float2bfloat16(mv[e]));
    }
    uint4 wv, mvv;
    wv.x  = pack_bf(w2v[0], w2v[1]);
    wv.y  = pack_bf(w2v[2], w2v[3]);
    wv.z  = pack_bf(w2v[0] - w2hi[0], w2v[1] - w2hi[1]);
    wv.w  = pack_bf(w2v[2] - w2hi[2], w2v[3] - w2hi[3]);
    mvv.x = pack_bf(mv[0], mv[1]);
    mvv.y = pack_bf(mv[2], mv[3]);
    mvv.z = pack_bf(mv[0] - mhi[0], mv[1] - mhi[1]);
    mvv.w = pack_bf(mv[2] - mhi[2], mv[3] - mhi[3]);
    g_bw2[idx] = wv;
    g_bm[idx]  = mvv;
}

// ---------------- main kernel ----------------
__global__ __launch_bounds__(TPB, 1)
void cnf_mma_kernel(const float* __restrict__ z,
                    const float* __restrict__ t,
                    const float* __restrict__ W1, const float* __restrict__ b1,
                    const float* __restrict__ b2, const float* __restrict__ b3,
                    const float* __restrict__ W3,
                    float* __restrict__ dz_out, float* __restrict__ dlogp_out,
                    int B)
{
    extern __shared__ __align__(16) char sm[];
    const int tid = threadIdx.x;
    const int wid = tid >> 5;
    const int lane = tid & 31;
    const int g = lane >> 2;
    const int c = lane & 3;
    const int bp = wid & 3;            // m-block pair: blocks 2bp, 2bp+1
    const int jg = (wid >> 2) & 1;     // jt quartet within half
    const int nh = wid >> 3;           // which N-half

    float* W1s = (float*)(sm + OFF_W1);
    float* W3s = (float*)(sm + OFF_W3);
    float* b1s = (float*)(sm + OFF_B1);
    float* b2s = (float*)(sm + OFF_B2);
    float* b3s = (float*)(sm + OFF_B3);
    float* redu = (float*)(sm + OFF_REDU);

    // ---- stage misc weights ----
    for (int i = tid; i < 9 * HD; i += TPB) W1s[i] = W1[i];
    for (int i = tid; i < HD * DD; i += TPB) W3s[i] = W3[i];
    if (tid < HD) { b1s[tid] = b1[tid]; b2s[tid] = b2[tid]; }
    if (tid < DD) b3s[tid] = b3[tid];
    __syncthreads();

    // ---- layer 1: thread = (sample s_loc, k-quarter kq); 32 h1 values; permuted scatter ----
    {
        const int s_loc = tid & 127;
        const int kq = tid >> 7;
        const int sample0 = blockIdx.x * SPB + s_loc;
        float zr[DD];
        if (sample0 < B) {
            const float4* zv = (const float4*)(z + (size_t)sample0 * DD);
            float4 za = zv[0], zb = zv[1];
            zr[0]=za.x; zr[1]=za.y; zr[2]=za.z; zr[3]=za.w;
            zr[4]=zb.x; zr[5]=zb.y; zr[6]=zb.z; zr[7]=zb.w;
        } else {
#pragma unroll
            for (int d = 0; d < DD; d++) zr[d] = 0.0f;
        }
        const float tv = t[0];
        float h[32];
        const int kbase = kq * 32;
#pragma unroll
        for (int kk = 0; kk < 32; kk += 4) {
            float4 acc = *(const float4*)&b1s[kbase + kk];
#pragma unroll
            for (int d = 0; d < DD; d++) {
                float4 w = *(const float4*)&W1s[d * HD + kbase + kk];
                acc.x = fmaf(zr[d], w.x, acc.x);
                acc.y = fmaf(zr[d], w.y, acc.y);
                acc.z = fmaf(zr[d], w.z, acc.z);
                acc.w = fmaf(zr[d], w.w, acc.w);
            }
            float4 w8 = *(const float4*)&W1s[8 * HD + kbase + kk];
            h[kk + 0] = fast_tanh(fmaf(tv, w8.x, acc.x));
            h[kk + 1] = fast_tanh(fmaf(tv, w8.y, acc.y));
            h[kk + 2] = fast_tanh(fmaf(tv, w8.z, acc.z));
            h[kk + 3] = fast_tanh(fmaf(tv, w8.w, acc.w));
        }
        const int blk_a = s_loc >> 4;
        const int rowin = s_loc & 15;
        const int g_a = rowin & 7;
        const int regrow = rowin >> 3;
#pragma unroll
        for (int i = 0; i < 16; i++) {
            const int kp = kq * 16 + i;
            const int s  = kp >> 3;
            const int w8 = kp & 7;
            const int cc = w8 & 3;
            const int reg = ((w8 >> 2) << 1) + regrow;
            const int loc = (g_a ^ (cc << 1)) | (cc << 3);
            const uint32_t off = (uint32_t)((((blk_a * 8 + s) * 32) + loc) * 16 + reg * 4);
            float x0 = h[2 * i], x1 = h[2 * i + 1];
            uint hi, lo;
            split_pack(x0, x1, hi, lo);
            *(uint*)(sm + OFF_H1HI + off) = hi;
            *(uint*)(sm + OFF_H1LO + off) = lo;
            float q0 = fmaf(-x0, x0, 1.0f);
            float q1 = fmaf(-x1, x1, 1.0f);
            split_pack(q0, q1, hi, lo);
            *(uint*)(sm + OFF_S1HI + off) = hi;
            *(uint*)(sm + OFF_S1LO + off) = lo;
        }
    }
    __syncthreads();

    // ---- GEMMs: warp = (nh, jg, bp); A from smem, B by LDG (L2-resident) ----
    const uint32_t aloc = (uint32_t)(((g ^ (c << 1)) | (c << 3)) * 16);
    const int jtb = nh * 8 + jg * 4;

    float acc1[2][4][4], acc2[2][4][4];
#pragma unroll
    for (int bb = 0; bb < 2; bb++)
#pragma unroll
        for (int q = 0; q < 4; q++)
#pragma unroll
            for (int e = 0; e < 4; e++) { acc1[bb][q][e] = 0.0f; acc2[bb][q][e] = 0.0f; }

#pragma unroll
    for (int s = 0; s < 8; s++) {
        uint4 h1h[2], h1l[2], s1h[2], s1l[2];
#pragma unroll
        for (int bb = 0; bb < 2; bb++) {
            const uint32_t ao = (uint32_t)(((2 * bp + bb) * 8 + s) * 512) + aloc;
            h1h[bb] = *(const uint4*)(sm + OFF_H1HI + ao);
            h1l[bb] = *(const uint4*)(sm + OFF_H1LO + ao);
            s1h[bb] = *(const uint4*)(sm + OFF_S1HI + ao);
            s1l[bb] = *(const uint4*)(sm + OFF_S1LO + ao);
        }
#pragma unroll
        for (int q = 0; q < 4; q++) {
            const int bi = ((jtb + q) * 8 + s) * 32 + lane;
            const uint4 wv = g_bw2[bi];
            const uint4 mv = g_bm[bi];
#pragma unroll
            for (int bb = 0; bb < 2; bb++) {
                mma_bf16(acc1[bb][q], h1h[bb].x, h1h[bb].y, h1h[bb].z, h1h[bb].w, wv.x, wv.y);
                mma_bf16(acc1[bb][q], h1h[bb].x, h1h[bb].y, h1h[bb].z, h1h[bb].w, wv.z, wv.w);
                mma_bf16(acc1[bb][q], h1l[bb].x, h1l[bb].y, h1l[bb].z, h1l[bb].w, wv.x, wv.y);
                mma_bf16(acc2[bb][q], s1h[bb].x, s1h[bb].y, s1h[bb].z, s1h[bb].w, mv.x, mv.y);
                mma_bf16(acc2[bb][q], s1h[bb].x, s1h[bb].y, s1h[bb].z, s1h[bb].w, mv.z, mv.w);
                mma_bf16(acc2[bb][q], s1l[bb].x, s1l[bb].y, s1l[bb].z, s1l[bb].w, mv.x, mv.y);
            }
        }
    }

    // ---- epilogue (single nh half per warp) ----
    ull dz[2][2][4];
    float tr[2][2] = {{0.f, 0.f}, {0.f, 0.f}};
#pragma unroll
    for (int bb = 0; bb < 2; bb++)
#pragma unroll
        for (int r = 0; r < 2; r++)
#pragma unroll
            for (int e = 0; e < 4; e++) dz[bb][r][e] = 0ULL;

#pragma unroll
    for (int q = 0; q < 4; q++) {
        const int j0 = (jtb + q) * 8 + 2 * c;
        const float b2x = b2s[j0], b2y = b2s[j0 + 1];
        const ull* w30 = (const ull*)(W3s + j0 * DD);
        const ull* w31 = (const ull*)(W3s + (j0 + 1) * DD);
#pragma unroll
        for (int bb = 0; bb < 2; bb++) {
            {
                float h2 = fast_tanh(acc1[bb][q][0] + b2x);
                tr[bb][0] = fmaf(acc2[bb][q][0], fmaf(-h2, h2, 1.0f), tr[bb][0]);
                ull hp = pack2(h2, h2);
                dz[bb][0][0] = fma2(hp, w30[0], dz[bb][0][0]);
                dz[bb][0][1] = fma2(hp, w30[1], dz[bb][0][1]);
                dz[bb][0][2] = fma2(hp, w30[2], dz[bb][0][2]);
                dz[bb][0][3] = fma2(hp, w30[3], dz[bb][0][3]);
            }
            {
                float h2 = fast_tanh(acc1[bb][q][1] + b2y);
                tr[bb][0] = fmaf(acc2[bb][q][1], fmaf(-h2, h2, 1.0f), tr[bb][0]);
                ull hp = pack2(h2, h2);
                dz[bb][0][0] = fma2(hp, w31[0], dz[bb][0][0]);
                dz[bb][0][1] = fma2(hp, w31[1], dz[bb][0][1]);
                dz[bb][0][2] = fma2(hp, w31[2], dz[bb][0][2]);
                dz[bb][0][3] = fma2(hp, w31[3], dz[bb][0][3]);
            }
            {
                float h2 = fast_tanh(acc1[bb][q][2] + b2x);
                tr[bb][1] = fmaf(acc2[bb][q][2], fmaf(-h2, h2, 1.0f), tr[bb][1]);
                ull hp = pack2(h2, h2);
                dz[bb][1][0] = fma2(hp, w30[0], dz[bb][1][0]);
                dz[bb][1][1] = fma2(hp, w30[1], dz[bb][1][1]);
                dz[bb][1][2] = fma2(hp, w30[2], dz[bb][1][2]);
                dz[bb][1][3] = fma2(hp, w30[3], dz[bb][1][3]);
            }
            {
                float h2 = fast_tanh(acc1[bb][q][3] + b2y);
                tr[bb][1] = fmaf(acc2[bb][q][3], fmaf(-h2, h2, 1.0f), tr[bb][1]);
                ull hp = pack2(h2, h2);
                dz[bb][1][0] = fma2(hp, w31[0], dz[bb][1][0]);
                dz[bb][1][1] = fma2(hp, w31[1], dz[bb][1][1]);
                dz[bb][1][2] = fma2(hp, w31[2], dz[bb][1][2]);
                dz[bb][1][3] = fma2(hp, w31[3], dz[bb][1][3]);
            }
        }
    }

    // ---- reduce over the 4 c-lanes ----
#pragma unroll
    for (int off = 1; off <= 2; off <<= 1) {
#pragma unroll
        for (int bb = 0; bb < 2; bb++)
#pragma unroll
            for (int r = 0; r < 2; r++) {
                tr[bb][r] += __shfl_xor_sync(0xffffffffu, tr[bb][r], off);
#pragma unroll
                for (int e = 0; e < 4; e++)
                    dz[bb][r][e] = add2(dz[bb][r][e], __shfl_xor_sync(0xffffffffu, dz[bb][r][e], off));
            }
    }

    // ---- cross-warp combine: slots 0-2 stage, slot 3 (nh=1,jg=1) finishes ----
    const int slot = nh * 2 + jg;
    __syncthreads();
    if (slot < 3 && c == 0) {
#pragma unroll
        for (int bb = 0; bb < 2; bb++)
#pragma unroll
            for (int r = 0; r < 2; r++) {
                const int sl = (2 * bp + bb) * 16 + r * 8 + g;
                float* rp = redu + sl * 30 + slot * 10;
                float2 v;
                v = unpack2(dz[bb][r][0]); rp[0] = v.x; rp[1] = v.y;
                v = unpack2(dz[bb][r][1]); rp[2] = v.x; rp[3] = v.y;
                v = unpack2(dz[bb][r][2]); rp[4] = v.x; rp[5] = v.y;
                v = unpack2(dz[bb][r][3]); rp[6] = v.x; rp[7] = v.y;
                rp[8] = tr[bb][r];
            }
    }
    __syncthreads();
    if (slot == 3 && c == 0) {
        float4 b3a = *(const float4*)&b3s[0];
        float4 b3b = *(const float4*)&b3s[4];
#pragma unroll
        for (int bb = 0; bb < 2; bb++)
#pragma unroll
            for (int r = 0; r < 2; r++) {
                const int sl = (2 * bp + bb) * 16 + r * 8 + g;
                const int sample = blockIdx.x * SPB + sl;
                const float* rp = redu + sl * 30;
                float o[8];
                float2 v0 = unpack2(dz[bb][r][0]), v1 = unpack2(dz[bb][r][1]);
                float2 v2 = unpack2(dz[bb][r][2]), v3 = unpack2(dz[bb][r][3]);
                o[0]=v0.x; o[1]=v0.y; o[2]=v1.x; o[3]=v1.y;
                o[4]=v2.x; o[5]=v2.y; o[6]=v3.x; o[7]=v3.y;
                float trs = tr[bb][r];
#pragma unroll
                for (int sslot = 0; sslot < 3; sslot++) {
                    const float* q = rp + sslot * 10;
#pragma unroll
                    for (int e = 0; e < 8; e++) o[e] += q[e];
                    trs += q[8];
                }
                if (sample < B) {
                    float4* ov = (float4*)(dz_out + (size_t)sample * DD);
                    ov[0] = make_float4(o[0] + b3a.x, o[1] + b3a.y, o[2] + b3a.z, o[3] + b3a.w);
                    ov[1] = make_float4(o[4] + b3b.x, o[5] + b3b.y, o[6] + b3b.z, o[7] + b3b.w);
                    dlogp_out[sample] = -trs;
                }
            }
    }
}

extern "C" void kernel_launch(void* const* d_in, const int* in_sizes, int n_in,
                              void* d_out, int out_size) {
    const float* z  = (const float*)d_in[0];
    // d_in[1] = logp_z (unused: dlogp/dt = -trace only)
    const float* t  = (const float*)d_in[2];
    const float* W1 = (const float*)d_in[3];
    const float* b1 = (const float*)d_in[4];
    const float* W2 = (const float*)d_in[5];
    const float* b2 = (const float*)d_in[6];
    const float* W3 = (const float*)d_in[7];
    const float* b3 = (const float*)d_in[8];

    const int B = in_sizes[0] / DD;
    float* dz_out    = (float*)d_out;
    float* dlogp_out = dz_out + (size_t)B * DD;

    setup_kernel<<<16, 256>>>(W1, W2, W3);

    cudaFuncSetAttribute(cnf_mma_kernel,
                         cudaFuncAttributeMaxDynamicSharedMemorySize, SMEM_BYTES);
    cnf_mma_kernel<<<(B + SPB - 1) / SPB, TPB, SMEM_BYTES>>>(
        z, t, W1, b1, b2, b3, W3, dz_out, dlogp_out, B);
}